// round 1
// baseline (speedup 1.0000x reference)
#include <cuda_runtime.h>
#include <math.h>

#define BB    4
#define SS    2048
#define DD    512
#define HH    8
#define PHDD  64
#define BHH   (BB*HH)      // 32
#define LL    2048         // per-head seq length after .view
#define MROWS (BB*SS)      // 8192
#define SCALE 0.04419417382415922f   // 512^-0.5
#define EPSF  1e-9f

// Scratch (allocation-free rule: __device__ globals)
__device__ float g_q[MROWS*DD];
__device__ float g_k[MROWS*DD];
__device__ float g_v[MROWS*DD];
__device__ float g_ctx[MROWS*DD];
__device__ float g_x[MROWS*DD];

// ---------------------------------------------------------------------------
// C[M,N] = A[M,K] @ W[N,K]^T + bias  (+ residual)
// 128x128 block tile, BK=8, 256 threads, 8x8 per thread.
// ---------------------------------------------------------------------------
template<bool ADD_RES>
__global__ __launch_bounds__(256)
void sgemm_bias(const float* __restrict__ A, const float* __restrict__ W,
                const float* __restrict__ bias, const float* __restrict__ res,
                float* __restrict__ C, int Mdim, int Ndim, int Kdim)
{
    __shared__ float As[8][128];
    __shared__ float Bs[8][128];

    const int t  = threadIdx.x;
    const int bm = blockIdx.y, bn = blockIdx.x;
    const int ty = t >> 4, tx = t & 15;
    const int lr = t >> 1;            // 0..127
    const int lc = (t & 1) * 4;       // 0 or 4

    const float* Arow = A + (size_t)(bm*128 + lr) * Kdim + lc;
    const float* Wrow = W + (size_t)(bn*128 + lr) * Kdim + lc;

    float acc[8][8];
    #pragma unroll
    for (int i = 0; i < 8; i++)
        #pragma unroll
        for (int j = 0; j < 8; j++) acc[i][j] = 0.f;

    for (int k0 = 0; k0 < Kdim; k0 += 8) {
        float4 av = *(const float4*)(Arow + k0);
        float4 wv = *(const float4*)(Wrow + k0);
        As[lc+0][lr] = av.x; As[lc+1][lr] = av.y;
        As[lc+2][lr] = av.z; As[lc+3][lr] = av.w;
        Bs[lc+0][lr] = wv.x; Bs[lc+1][lr] = wv.y;
        Bs[lc+2][lr] = wv.z; Bs[lc+3][lr] = wv.w;
        __syncthreads();

        #pragma unroll
        for (int kk = 0; kk < 8; kk++) {
            float a[8], b[8];
            #pragma unroll
            for (int i = 0; i < 8; i++) a[i] = As[kk][ty*8 + i];
            #pragma unroll
            for (int j = 0; j < 8; j++) b[j] = Bs[kk][tx*8 + j];
            #pragma unroll
            for (int i = 0; i < 8; i++)
                #pragma unroll
                for (int j = 0; j < 8; j++)
                    acc[i][j] += a[i] * b[j];
        }
        __syncthreads();
    }

    #pragma unroll
    for (int i = 0; i < 8; i++) {
        const int m = bm*128 + ty*8 + i;
        #pragma unroll
        for (int j = 0; j < 8; j += 4) {
            const int n = bn*128 + tx*8 + j;
            float4 bv4 = *(const float4*)(bias + n);
            float4 o4;
            o4.x = acc[i][j+0] + bv4.x;
            o4.y = acc[i][j+1] + bv4.y;
            o4.z = acc[i][j+2] + bv4.z;
            o4.w = acc[i][j+3] + bv4.w;
            if (ADD_RES) {
                float4 r4 = *(const float4*)(res + (size_t)m*Ndim + n);
                o4.x += r4.x; o4.y += r4.y; o4.z += r4.z; o4.w += r4.w;
            }
            *(float4*)(C + (size_t)m*Ndim + n) = o4;
        }
    }
}

// ---------------------------------------------------------------------------
// Attention: one block per (head, 16-row query tile).
// Full 16x2048 score tile in smem -> exact softmax -> write attn -> P@V.
// ---------------------------------------------------------------------------
__global__ __launch_bounds__(256)
void attn_kernel(const float* __restrict__ q, const float* __restrict__ k,
                 const float* __restrict__ v, float* __restrict__ attn,
                 float* __restrict__ ctx)
{
    extern __shared__ float sm[];
    float* sS = sm;                 // [16][2048]
    float* sQ = sm + 16*2048;       // [16][64]
    __shared__ float sInv[16];

    const int t  = threadIdx.x;
    const int bh = blockIdx.y;
    const int q0 = blockIdx.x * 16;

    const float* qh = q + (size_t)bh * (LL*PHDD);
    const float* kh = k + (size_t)bh * (LL*PHDD);
    const float* vh = v + (size_t)bh * (LL*PHDD);

    // load Q tile (16 x 64)
    {
        const int r = t >> 4;
        const int c = (t & 15) * 4;
        *(float4*)(sQ + r*64 + c) = *(const float4*)(qh + (size_t)(q0 + r)*64 + c);
    }
    __syncthreads();

    // phase 1: scores S = Q K^T * scale (each thread owns k-rows j = t, t+256, ...)
    for (int j = t; j < LL; j += 256) {
        const float* krow = kh + (size_t)j * 64;
        float acc[16];
        #pragma unroll
        for (int i = 0; i < 16; i++) acc[i] = 0.f;
        #pragma unroll
        for (int c4 = 0; c4 < 16; c4++) {
            float4 kv = *(const float4*)(krow + c4*4);
            #pragma unroll
            for (int i = 0; i < 16; i++) {
                float4 qv = *(const float4*)(sQ + i*64 + c4*4);
                acc[i] += qv.x*kv.x + qv.y*kv.y + qv.z*kv.z + qv.w*kv.w;
            }
        }
        #pragma unroll
        for (int i = 0; i < 16; i++) sS[i*2048 + j] = acc[i] * SCALE;
    }
    __syncthreads();

    // phase 2: exact softmax stats (16 threads per row)
    {
        const int r = t >> 4, g = t & 15;
        float* srow = sS + r*2048;
        float mx = -1e30f;
        for (int j = g; j < 2048; j += 16) mx = fmaxf(mx, srow[j]);
        #pragma unroll
        for (int o = 8; o >= 1; o >>= 1) mx = fmaxf(mx, __shfl_xor_sync(0xffffffffu, mx, o));
        float ssum = 0.f;
        for (int j = g; j < 2048; j += 16) {
            float e = __expf(srow[j] - mx);
            srow[j] = e;
            ssum += e;
        }
        #pragma unroll
        for (int o = 8; o >= 1; o >>= 1) ssum += __shfl_xor_sync(0xffffffffu, ssum, o);
        if (g == 0) sInv[r] = 1.f / ssum;
    }
    __syncthreads();

    // phase 2b: normalize in smem + stream attn to gmem (coalesced float4)
    float* attn_tile = attn + (size_t)bh * LL * LL + (size_t)q0 * LL;  // 16x2048 contiguous
    for (int idx4 = t; idx4 < (16*2048)/4; idx4 += 256) {
        const int row = idx4 >> 9;
        const float inv = sInv[row];
        float4 e = ((float4*)sS)[idx4];
        e.x *= inv; e.y *= inv; e.z *= inv; e.w *= inv;
        ((float4*)sS)[idx4] = e;
        ((float4*)attn_tile)[idx4] = e;
    }
    __syncthreads();

    // phase 3: ctx(16x64) = P(16x2048) @ V(2048x64)
    {
        const int r = t >> 4, cg = t & 15;
        const float* prow = sS + r*2048;
        float4 acc = make_float4(0.f, 0.f, 0.f, 0.f);
        #pragma unroll 4
        for (int j = 0; j < 2048; j += 4) {
            const float p0 = prow[j], p1 = prow[j+1], p2 = prow[j+2], p3 = prow[j+3];
            float4 v0 = *(const float4*)(vh + (size_t)(j+0)*64 + cg*4);
            float4 v1 = *(const float4*)(vh + (size_t)(j+1)*64 + cg*4);
            float4 v2 = *(const float4*)(vh + (size_t)(j+2)*64 + cg*4);
            float4 v3 = *(const float4*)(vh + (size_t)(j+3)*64 + cg*4);
            acc.x += p0*v0.x + p1*v1.x + p2*v2.x + p3*v3.x;
            acc.y += p0*v0.y + p1*v1.y + p2*v2.y + p3*v3.y;
            acc.z += p0*v0.z + p1*v1.z + p2*v2.z + p3*v3.z;
            acc.w += p0*v0.w + p1*v1.w + p2*v2.w + p3*v3.w;
        }
        *(float4*)(ctx + (size_t)bh*(LL*PHDD) + (size_t)(q0 + r)*64 + cg*4) = acc;
    }
}

// ---------------------------------------------------------------------------
// LayerNorm (torch variant: unbiased std, eps added to std). One warp per row.
// ---------------------------------------------------------------------------
__global__ __launch_bounds__(256)
void ln_kernel(const float* __restrict__ x, const float* __restrict__ wa,
               const float* __restrict__ wb, float* __restrict__ out)
{
    const int warp = threadIdx.x >> 5, lane = threadIdx.x & 31;
    const int row = blockIdx.x * 8 + warp;
    const float* xr = x + (size_t)row * DD;

    float4 vals[4];
    float s = 0.f, ss = 0.f;
    #pragma unroll
    for (int p = 0; p < 4; p++) {
        vals[p] = *(const float4*)(xr + p*128 + lane*4);
        s  += vals[p].x + vals[p].y + vals[p].z + vals[p].w;
        ss += vals[p].x*vals[p].x + vals[p].y*vals[p].y
            + vals[p].z*vals[p].z + vals[p].w*vals[p].w;
    }
    #pragma unroll
    for (int o = 16; o >= 1; o >>= 1) {
        s  += __shfl_xor_sync(0xffffffffu, s,  o);
        ss += __shfl_xor_sync(0xffffffffu, ss, o);
    }
    const float mean = s * (1.f/512.f);
    const float var  = (ss - 512.f*mean*mean) * (1.f/511.f);   // ddof=1
    const float stdv = sqrtf(fmaxf(var, 0.f));
    const float rinv = 1.f / (stdv + EPSF);

    #pragma unroll
    for (int p = 0; p < 4; p++) {
        const int c = p*128 + lane*4;
        float4 a = *(const float4*)(wa + c);
        float4 b = *(const float4*)(wb + c);
        float4 o4;
        o4.x = a.x*(vals[p].x - mean)*rinv + b.x;
        o4.y = a.y*(vals[p].y - mean)*rinv + b.y;
        o4.z = a.z*(vals[p].z - mean)*rinv + b.z;
        o4.w = a.w*(vals[p].w - mean)*rinv + b.w;
        *(float4*)(out + (size_t)row*DD + c) = o4;
    }
}

// ---------------------------------------------------------------------------
extern "C" void kernel_launch(void* const* d_in, const int* in_sizes, int n_in,
                              void* d_out, int out_size)
{
    const float* key   = (const float*)d_in[0];
    const float* value = (const float*)d_in[1];
    const float* query = (const float*)d_in[2];
    const float* Wq = (const float*)d_in[3];  const float* bq = (const float*)d_in[4];
    const float* Wk = (const float*)d_in[5];  const float* bk = (const float*)d_in[6];
    const float* Wv = (const float*)d_in[7];  const float* bv = (const float*)d_in[8];
    const float* Wo = (const float*)d_in[9];  const float* bo = (const float*)d_in[10];
    const float* wa = (const float*)d_in[11]; const float* wb = (const float*)d_in[12];

    float* out  = (float*)d_out;                    // [B,S,D] = 4,194,304 floats
    float* attn = out + (size_t)MROWS * DD;         // [B*H,L,L] = 134,217,728 floats

    float *pq, *pk, *pv, *pctx, *px;
    cudaGetSymbolAddress((void**)&pq,   g_q);
    cudaGetSymbolAddress((void**)&pk,   g_k);
    cudaGetSymbolAddress((void**)&pv,   g_v);
    cudaGetSymbolAddress((void**)&pctx, g_ctx);
    cudaGetSymbolAddress((void**)&px,   g_x);

    dim3 gg(DD/128, MROWS/128);   // (4, 64)
    sgemm_bias<false><<<gg, 256>>>(query, Wq, bq, nullptr, pq, MROWS, DD, DD);
    sgemm_bias<false><<<gg, 256>>>(key,   Wk, bk, nullptr, pk, MROWS, DD, DD);
    sgemm_bias<false><<<gg, 256>>>(value, Wv, bv, nullptr, pv, MROWS, DD, DD);

    const int smem_bytes = (16*2048 + 16*64) * (int)sizeof(float);  // 135168
    cudaFuncSetAttribute(attn_kernel, cudaFuncAttributeMaxDynamicSharedMemorySize, smem_bytes);
    attn_kernel<<<dim3(LL/16, BHH), 256, smem_bytes>>>(pq, pk, pv, attn, pctx);

    sgemm_bias<true><<<gg, 256>>>(pctx, Wo, bo, query, px, MROWS, DD, DD);
    ln_kernel<<<MROWS/8, 256>>>(px, wa, wb, out);
}

// round 2
// speedup vs baseline: 5.7558x; 5.7558x over previous
#include <cuda_runtime.h>
#include <math.h>

#define BB    4
#define SS    2048
#define DD    512
#define HH    8
#define PHDD  64
#define BHH   (BB*HH)      // 32
#define LL    2048
#define MROWS (BB*SS)      // 8192
#define SCALE 0.04419417382415922f   // 512^-0.5
#define EPSF  1e-9f

// Scratch (__device__ globals: allocation-free rule)
__device__ float g_q[MROWS*DD];
__device__ float g_k[MROWS*DD];
__device__ float g_v[MROWS*DD];
__device__ float g_vT[MROWS*DD];
__device__ float g_ctx[MROWS*DD];
__device__ float g_x[MROWS*DD];

// ---------------------------------------------------------------------------
__device__ __forceinline__ float to_tf32(float x) {
    float r;
    asm("cvt.rna.tf32.f32 %0, %1;" : "=f"(r) : "f"(x));
    return r;
}

__device__ __forceinline__ void mma_tf32(float (&c)[4],
                                         float a0, float a1, float a2, float a3,
                                         float b0, float b1)
{
    asm volatile(
        "mma.sync.aligned.m16n8k8.row.col.f32.tf32.tf32.f32 "
        "{%0,%1,%2,%3}, {%4,%5,%6,%7}, {%8,%9}, {%0,%1,%2,%3};\n"
        : "+f"(c[0]), "+f"(c[1]), "+f"(c[2]), "+f"(c[3])
        : "r"(__float_as_uint(a0)), "r"(__float_as_uint(a1)),
          "r"(__float_as_uint(a2)), "r"(__float_as_uint(a3)),
          "r"(__float_as_uint(b0)), "r"(__float_as_uint(b1)));
}

// ---------------------------------------------------------------------------
// TF32 GEMM: C[8192,512] = A[8192,512] @ W[512,512]^T + bias (+ residual)
// 128x128 CTA tile, BK=16, 8 warps (2x4), warp tile 64x32.
// ---------------------------------------------------------------------------
#define GP 20   // smem pitch (20 % 32 == 20; lr*20+lc conflict-free per quad set)

template<bool ADD_RES>
__global__ __launch_bounds__(256)
void gemm_tf32(const float* __restrict__ A, const float* __restrict__ W,
               const float* __restrict__ bias, const float* __restrict__ res,
               float* __restrict__ C)
{
    __shared__ float sA[128*GP];
    __shared__ float sB[128*GP];

    const int t    = threadIdx.x;
    const int warp = t >> 5, lane = t & 31;
    const int lr   = lane >> 2, lc = lane & 3;
    const int wm   = warp >> 2, wn = warp & 3;       // 2 x 4 warp grid
    const int bm   = blockIdx.y, bn = blockIdx.x;

    float acc[4][4][4];
    #pragma unroll
    for (int i = 0; i < 4; i++)
        #pragma unroll
        for (int j = 0; j < 4; j++)
            #pragma unroll
            for (int r = 0; r < 4; r++) acc[i][j][r] = 0.f;

    for (int k0 = 0; k0 < 512; k0 += 16) {
        // load A,W tiles (128x16 each), cvt to tf32
        #pragma unroll
        for (int i = 0; i < 2; i++) {
            const int f   = 2*t + i;          // 0..511 float4 slots
            const int row = f >> 2;
            const int c4  = (f & 3) << 2;
            float4 av = *(const float4*)(A + (size_t)(bm*128 + row)*512 + k0 + c4);
            sA[row*GP + c4 + 0] = to_tf32(av.x);
            sA[row*GP + c4 + 1] = to_tf32(av.y);
            sA[row*GP + c4 + 2] = to_tf32(av.z);
            sA[row*GP + c4 + 3] = to_tf32(av.w);
            float4 wv = *(const float4*)(W + (size_t)(bn*128 + row)*512 + k0 + c4);
            sB[row*GP + c4 + 0] = to_tf32(wv.x);
            sB[row*GP + c4 + 1] = to_tf32(wv.y);
            sB[row*GP + c4 + 2] = to_tf32(wv.z);
            sB[row*GP + c4 + 3] = to_tf32(wv.w);
        }
        __syncthreads();

        #pragma unroll
        for (int kk = 0; kk < 2; kk++) {
            const int kb = kk*8;
            float a[4][4], b[4][2];
            #pragma unroll
            for (int mf = 0; mf < 4; mf++) {
                const int rb = (wm*64 + mf*16 + lr)*GP + kb + lc;
                a[mf][0] = sA[rb];
                a[mf][1] = sA[rb + 8*GP];
                a[mf][2] = sA[rb + 4];
                a[mf][3] = sA[rb + 8*GP + 4];
            }
            #pragma unroll
            for (int nf = 0; nf < 4; nf++) {
                const int rb = (wn*32 + nf*8 + lr)*GP + kb + lc;
                b[nf][0] = sB[rb];
                b[nf][1] = sB[rb + 4];
            }
            #pragma unroll
            for (int mf = 0; mf < 4; mf++)
                #pragma unroll
                for (int nf = 0; nf < 4; nf++)
                    mma_tf32(acc[mf][nf], a[mf][0], a[mf][1], a[mf][2], a[mf][3],
                             b[nf][0], b[nf][1]);
        }
        __syncthreads();
    }

    // epilogue
    #pragma unroll
    for (int mf = 0; mf < 4; mf++) {
        const int row = bm*128 + wm*64 + mf*16 + lr;
        #pragma unroll
        for (int nf = 0; nf < 4; nf++) {
            const int col = bn*128 + wn*32 + nf*8 + 2*lc;
            float2 bv = *(const float2*)(bias + col);
            float2 o0 = make_float2(acc[mf][nf][0] + bv.x, acc[mf][nf][1] + bv.y);
            float2 o1 = make_float2(acc[mf][nf][2] + bv.x, acc[mf][nf][3] + bv.y);
            if (ADD_RES) {
                float2 r0 = *(const float2*)(res + (size_t)row*512 + col);
                float2 r1 = *(const float2*)(res + (size_t)(row+8)*512 + col);
                o0.x += r0.x; o0.y += r0.y; o1.x += r1.x; o1.y += r1.y;
            }
            *(float2*)(C + (size_t)row*512 + col)     = o0;
            *(float2*)(C + (size_t)(row+8)*512 + col) = o1;
        }
    }
}

// ---------------------------------------------------------------------------
// V transpose per head: g_v [head][j 2048][d 64] -> g_vT [head][d 64][j 2048]
// ---------------------------------------------------------------------------
__global__ __launch_bounds__(256)
void transpose_v(const float* __restrict__ v, float* __restrict__ vT)
{
    __shared__ float ts[128*65];
    const int t = threadIdx.x;
    const int head = blockIdx.y;
    const int j0 = blockIdx.x * 128;
    const float* vh = v + (size_t)head * (LL*PHDD);

    #pragma unroll
    for (int p = 0; p < 8; p++) {
        const int f = t + p*256;          // 0..2047
        const int row = f >> 4, c4 = (f & 15) << 2;
        float4 val = *(const float4*)(vh + (size_t)(j0 + row)*64 + c4);
        ts[row*65 + c4 + 0] = val.x;
        ts[row*65 + c4 + 1] = val.y;
        ts[row*65 + c4 + 2] = val.z;
        ts[row*65 + c4 + 3] = val.w;
    }
    __syncthreads();
    float* vth = vT + (size_t)head * (LL*PHDD);
    #pragma unroll
    for (int p = 0; p < 8; p++) {
        const int f = t + p*256;
        const int d = f >> 5, c4 = (f & 31) << 2;
        float4 o;
        o.x = ts[(c4+0)*65 + d];
        o.y = ts[(c4+1)*65 + d];
        o.z = ts[(c4+2)*65 + d];
        o.w = ts[(c4+3)*65 + d];
        *(float4*)(vth + (size_t)d*2048 + j0 + c4) = o;
    }
}

// ---------------------------------------------------------------------------
// Fused attention, tensor cores. CTA = (head, 128 q rows). Two passes over
// 16 k-tiles of 128: pass1 online softmax stats, pass2 P write + PV.
// ---------------------------------------------------------------------------
#define QP 68    // sQ/sK pitch  (68 % 32 == 4 -> conflict-free frag loads)
#define SP 132   // sP/sVT pitch (132 % 32 == 4)

__global__ __launch_bounds__(256)
void attn_tc(const float* __restrict__ q, const float* __restrict__ k,
             const float* __restrict__ vT, float* __restrict__ attn,
             float* __restrict__ ctx)
{
    extern __shared__ float sm[];
    float* sQ  = sm;                    // 128*68
    float* sK  = sQ  + 128*QP;          // 128*68
    float* sVT = sK  + 128*QP;          // 64*132
    float* sP  = sVT + 64*SP;           // 128*132
    float* sM  = sP  + 128*SP;          // 128
    float* sI  = sM  + 128;             // 128
    float* sWm = sI  + 128;             // 4*128
    float* sWs = sWm + 512;             // 4*128

    const int t    = threadIdx.x;
    const int warp = t >> 5, lane = t & 31;
    const int lr   = lane >> 2, lc = lane & 3;
    const int wm   = warp >> 2, wn = warp & 3;   // QK^T map: 2 x 4
    const int pm   = warp >> 1, pn = warp & 1;   // PV map:   4 x 2

    const int head = blockIdx.y;
    const int q0   = blockIdx.x * 128;

    const float* qh  = q  + (size_t)head * (LL*PHDD);
    const float* kh  = k  + (size_t)head * (LL*PHDD);
    const float* vth = vT + (size_t)head * (LL*PHDD);

    // Q tile resident in smem (tf32)
    #pragma unroll
    for (int p = 0; p < 8; p++) {
        const int f = t + p*256;
        const int row = f >> 4, c4 = (f & 15) << 2;
        float4 val = *(const float4*)(qh + (size_t)(q0 + row)*64 + c4);
        sQ[row*QP + c4 + 0] = to_tf32(val.x);
        sQ[row*QP + c4 + 1] = to_tf32(val.y);
        sQ[row*QP + c4 + 2] = to_tf32(val.z);
        sQ[row*QP + c4 + 3] = to_tf32(val.w);
    }

    float run_m[4][2], run_s[4][2];
    #pragma unroll
    for (int mf = 0; mf < 4; mf++) {
        run_m[mf][0] = -1e30f; run_m[mf][1] = -1e30f;
        run_s[mf][0] = 0.f;    run_s[mf][1] = 0.f;
    }

    // ---------------- pass 1: online softmax stats ----------------
    for (int kt = 0; kt < 16; kt++) {
        const int j0 = kt * 128;
        #pragma unroll
        for (int p = 0; p < 8; p++) {
            const int f = t + p*256;
            const int row = f >> 4, c4 = (f & 15) << 2;
            float4 val = *(const float4*)(kh + (size_t)(j0 + row)*64 + c4);
            sK[row*QP + c4 + 0] = to_tf32(val.x);
            sK[row*QP + c4 + 1] = to_tf32(val.y);
            sK[row*QP + c4 + 2] = to_tf32(val.z);
            sK[row*QP + c4 + 3] = to_tf32(val.w);
        }
        __syncthreads();

        float acc[4][4][4];
        #pragma unroll
        for (int i = 0; i < 4; i++)
            #pragma unroll
            for (int j = 0; j < 4; j++)
                #pragma unroll
                for (int r = 0; r < 4; r++) acc[i][j][r] = 0.f;

        #pragma unroll
        for (int kk = 0; kk < 8; kk++) {
            const int kb = kk*8;
            float a[4][4], b[4][2];
            #pragma unroll
            for (int mf = 0; mf < 4; mf++) {
                const int rb = (wm*64 + mf*16 + lr)*QP + kb + lc;
                a[mf][0] = sQ[rb];       a[mf][1] = sQ[rb + 8*QP];
                a[mf][2] = sQ[rb + 4];   a[mf][3] = sQ[rb + 8*QP + 4];
            }
            #pragma unroll
            for (int nf = 0; nf < 4; nf++) {
                const int rb = (wn*32 + nf*8 + lr)*QP + kb + lc;
                b[nf][0] = sK[rb];       b[nf][1] = sK[rb + 4];
            }
            #pragma unroll
            for (int mf = 0; mf < 4; mf++)
                #pragma unroll
                for (int nf = 0; nf < 4; nf++)
                    mma_tf32(acc[mf][nf], a[mf][0], a[mf][1], a[mf][2], a[mf][3],
                             b[nf][0], b[nf][1]);
        }
        __syncthreads();

        // scale + online (m,s) update; rows lr (h=0) and lr+8 (h=1)
        #pragma unroll
        for (int mf = 0; mf < 4; mf++)
            #pragma unroll
            for (int nf = 0; nf < 4; nf++)
                #pragma unroll
                for (int r = 0; r < 4; r++) acc[mf][nf][r] *= SCALE;

        #pragma unroll
        for (int mf = 0; mf < 4; mf++) {
            #pragma unroll
            for (int h = 0; h < 2; h++) {
                float mx = -1e30f;
                #pragma unroll
                for (int nf = 0; nf < 4; nf++)
                    mx = fmaxf(mx, fmaxf(acc[mf][nf][2*h], acc[mf][nf][2*h+1]));
                mx = fmaxf(mx, __shfl_xor_sync(0xffffffffu, mx, 1));
                mx = fmaxf(mx, __shfl_xor_sync(0xffffffffu, mx, 2));
                const float nm = fmaxf(run_m[mf][h], mx);
                float s = 0.f;
                #pragma unroll
                for (int nf = 0; nf < 4; nf++)
                    s += __expf(acc[mf][nf][2*h]   - nm)
                       + __expf(acc[mf][nf][2*h+1] - nm);
                s += __shfl_xor_sync(0xffffffffu, s, 1);
                s += __shfl_xor_sync(0xffffffffu, s, 2);
                run_s[mf][h] = run_s[mf][h] * __expf(run_m[mf][h] - nm) + s;
                run_m[mf][h] = nm;
            }
        }
    }

    // merge per-warp stats across the 4 n-warps
    if ((lane & 3) == 0) {
        #pragma unroll
        for (int mf = 0; mf < 4; mf++)
            #pragma unroll
            for (int h = 0; h < 2; h++) {
                const int row = wm*64 + mf*16 + lr + h*8;
                sWm[wn*128 + row] = run_m[mf][h];
                sWs[wn*128 + row] = run_s[mf][h];
            }
    }
    __syncthreads();
    if (t < 128) {
        float M = sWm[t];
        M = fmaxf(M, sWm[128 + t]);
        M = fmaxf(M, sWm[256 + t]);
        M = fmaxf(M, sWm[384 + t]);
        float S = 0.f;
        #pragma unroll
        for (int w = 0; w < 4; w++)
            S += sWs[w*128 + t] * __expf(sWm[w*128 + t] - M);
        sM[t] = M;
        sI[t] = 1.f / S;
    }
    __syncthreads();

    // ---------------- pass 2: P write + PV ----------------
    float cacc[2][4][4];
    #pragma unroll
    for (int i = 0; i < 2; i++)
        #pragma unroll
        for (int j = 0; j < 4; j++)
            #pragma unroll
            for (int r = 0; r < 4; r++) cacc[i][j][r] = 0.f;

    for (int kt = 0; kt < 16; kt++) {
        const int j0 = kt * 128;
        #pragma unroll
        for (int p = 0; p < 8; p++) {
            const int f = t + p*256;
            const int row = f >> 4, c4 = (f & 15) << 2;
            float4 val = *(const float4*)(kh + (size_t)(j0 + row)*64 + c4);
            sK[row*QP + c4 + 0] = to_tf32(val.x);
            sK[row*QP + c4 + 1] = to_tf32(val.y);
            sK[row*QP + c4 + 2] = to_tf32(val.z);
            sK[row*QP + c4 + 3] = to_tf32(val.w);
        }
        #pragma unroll
        for (int p = 0; p < 8; p++) {
            const int f = t + p*256;
            const int d = f >> 5, c4 = (f & 31) << 2;
            float4 val = *(const float4*)(vth + (size_t)d*2048 + j0 + c4);
            sVT[d*SP + c4 + 0] = to_tf32(val.x);
            sVT[d*SP + c4 + 1] = to_tf32(val.y);
            sVT[d*SP + c4 + 2] = to_tf32(val.z);
            sVT[d*SP + c4 + 3] = to_tf32(val.w);
        }
        __syncthreads();

        // QK^T
        float acc[4][4][4];
        #pragma unroll
        for (int i = 0; i < 4; i++)
            #pragma unroll
            for (int j = 0; j < 4; j++)
                #pragma unroll
                for (int r = 0; r < 4; r++) acc[i][j][r] = 0.f;
        #pragma unroll
        for (int kk = 0; kk < 8; kk++) {
            const int kb = kk*8;
            float a[4][4], b[4][2];
            #pragma unroll
            for (int mf = 0; mf < 4; mf++) {
                const int rb = (wm*64 + mf*16 + lr)*QP + kb + lc;
                a[mf][0] = sQ[rb];       a[mf][1] = sQ[rb + 8*QP];
                a[mf][2] = sQ[rb + 4];   a[mf][3] = sQ[rb + 8*QP + 4];
            }
            #pragma unroll
            for (int nf = 0; nf < 4; nf++) {
                const int rb = (wn*32 + nf*8 + lr)*QP + kb + lc;
                b[nf][0] = sK[rb];       b[nf][1] = sK[rb + 4];
            }
            #pragma unroll
            for (int mf = 0; mf < 4; mf++)
                #pragma unroll
                for (int nf = 0; nf < 4; nf++)
                    mma_tf32(acc[mf][nf], a[mf][0], a[mf][1], a[mf][2], a[mf][3],
                             b[nf][0], b[nf][1]);
        }

        // p = exp(s - M) * inv -> sP (exact fp32)
        #pragma unroll
        for (int mf = 0; mf < 4; mf++) {
            #pragma unroll
            for (int h = 0; h < 2; h++) {
                const int row = wm*64 + mf*16 + lr + h*8;
                const float Mv = sM[row], Iv = sI[row];
                #pragma unroll
                for (int nf = 0; nf < 4; nf++) {
                    const int col = wn*32 + nf*8 + 2*lc;
                    float p0 = __expf(acc[mf][nf][2*h]   * SCALE - Mv) * Iv;
                    float p1 = __expf(acc[mf][nf][2*h+1] * SCALE - Mv) * Iv;
                    *(float2*)(sP + row*SP + col) = make_float2(p0, p1);
                }
            }
        }
        __syncthreads();

        // stream exact P to gmem + convert sP to tf32 in place
        float* attn_p = attn + ((size_t)head*2048 + q0) * 2048 + j0;
        #pragma unroll
        for (int p = 0; p < 16; p++) {
            const int f = t + p*256;          // 0..4095
            const int row = f >> 5, c4 = (f & 31) << 2;
            float4 val = *(const float4*)(sP + row*SP + c4);
            *(float4*)(attn_p + (size_t)row*2048 + c4) = val;
            val.x = to_tf32(val.x); val.y = to_tf32(val.y);
            val.z = to_tf32(val.z); val.w = to_tf32(val.w);
            *(float4*)(sP + row*SP + c4) = val;
        }
        __syncthreads();

        // PV: ctx += P(128x128) @ V(128x64)
        #pragma unroll
        for (int kk = 0; kk < 16; kk++) {
            const int kb = kk*8;
            float a[2][4], b[4][2];
            #pragma unroll
            for (int mf = 0; mf < 2; mf++) {
                const int rb = (pm*32 + mf*16 + lr)*SP + kb + lc;
                a[mf][0] = sP[rb];       a[mf][1] = sP[rb + 8*SP];
                a[mf][2] = sP[rb + 4];   a[mf][3] = sP[rb + 8*SP + 4];
            }
            #pragma unroll
            for (int nf = 0; nf < 4; nf++) {
                const int rb = (pn*32 + nf*8 + lr)*SP + kb + lc;
                b[nf][0] = sVT[rb];      b[nf][1] = sVT[rb + 4];
            }
            #pragma unroll
            for (int mf = 0; mf < 2; mf++)
                #pragma unroll
                for (int nf = 0; nf < 4; nf++)
                    mma_tf32(cacc[mf][nf], a[mf][0], a[mf][1], a[mf][2], a[mf][3],
                             b[nf][0], b[nf][1]);
        }
        __syncthreads();
    }

    // write ctx
    float* ch = ctx + (size_t)head * (LL*PHDD);
    #pragma unroll
    for (int mf = 0; mf < 2; mf++) {
        const int row = q0 + pm*32 + mf*16 + lr;
        #pragma unroll
        for (int nf = 0; nf < 4; nf++) {
            const int col = pn*32 + nf*8 + 2*lc;
            *(float2*)(ch + (size_t)row*64 + col)
                = make_float2(cacc[mf][nf][0], cacc[mf][nf][1]);
            *(float2*)(ch + (size_t)(row+8)*64 + col)
                = make_float2(cacc[mf][nf][2], cacc[mf][nf][3]);
        }
    }
}

// ---------------------------------------------------------------------------
// LayerNorm (torch variant: unbiased std, eps added to std). One warp per row.
// ---------------------------------------------------------------------------
__global__ __launch_bounds__(256)
void ln_kernel(const float* __restrict__ x, const float* __restrict__ wa,
               const float* __restrict__ wb, float* __restrict__ out)
{
    const int warp = threadIdx.x >> 5, lane = threadIdx.x & 31;
    const int row = blockIdx.x * 8 + warp;
    const float* xr = x + (size_t)row * DD;

    float4 vals[4];
    float s = 0.f, ss = 0.f;
    #pragma unroll
    for (int p = 0; p < 4; p++) {
        vals[p] = *(const float4*)(xr + p*128 + lane*4);
        s  += vals[p].x + vals[p].y + vals[p].z + vals[p].w;
        ss += vals[p].x*vals[p].x + vals[p].y*vals[p].y
            + vals[p].z*vals[p].z + vals[p].w*vals[p].w;
    }
    #pragma unroll
    for (int o = 16; o >= 1; o >>= 1) {
        s  += __shfl_xor_sync(0xffffffffu, s,  o);
        ss += __shfl_xor_sync(0xffffffffu, ss, o);
    }
    const float mean = s * (1.f/512.f);
    const float var  = (ss - 512.f*mean*mean) * (1.f/511.f);
    const float stdv = sqrtf(fmaxf(var, 0.f));
    const float rinv = 1.f / (stdv + EPSF);

    #pragma unroll
    for (int p = 0; p < 4; p++) {
        const int c = p*128 + lane*4;
        float4 a = *(const float4*)(wa + c);
        float4 b = *(const float4*)(wb + c);
        float4 o4;
        o4.x = a.x*(vals[p].x - mean)*rinv + b.x;
        o4.y = a.y*(vals[p].y - mean)*rinv + b.y;
        o4.z = a.z*(vals[p].z - mean)*rinv + b.z;
        o4.w = a.w*(vals[p].w - mean)*rinv + b.w;
        *(float4*)(out + (size_t)row*DD + c) = o4;
    }
}

// ---------------------------------------------------------------------------
extern "C" void kernel_launch(void* const* d_in, const int* in_sizes, int n_in,
                              void* d_out, int out_size)
{
    const float* key   = (const float*)d_in[0];
    const float* value = (const float*)d_in[1];
    const float* query = (const float*)d_in[2];
    const float* Wq = (const float*)d_in[3];  const float* bq = (const float*)d_in[4];
    const float* Wk = (const float*)d_in[5];  const float* bk = (const float*)d_in[6];
    const float* Wv = (const float*)d_in[7];  const float* bv = (const float*)d_in[8];
    const float* Wo = (const float*)d_in[9];  const float* bo = (const float*)d_in[10];
    const float* wa = (const float*)d_in[11]; const float* wb = (const float*)d_in[12];

    float* out  = (float*)d_out;
    float* attn = out + (size_t)MROWS * DD;

    float *pq, *pk, *pv, *pvT, *pctx, *px;
    cudaGetSymbolAddress((void**)&pq,   g_q);
    cudaGetSymbolAddress((void**)&pk,   g_k);
    cudaGetSymbolAddress((void**)&pv,   g_v);
    cudaGetSymbolAddress((void**)&pvT,  g_vT);
    cudaGetSymbolAddress((void**)&pctx, g_ctx);
    cudaGetSymbolAddress((void**)&px,   g_x);

    dim3 gg(DD/128, MROWS/128);   // (4, 64)
    gemm_tf32<false><<<gg, 256>>>(query, Wq, bq, nullptr, pq);
    gemm_tf32<false><<<gg, 256>>>(key,   Wk, bk, nullptr, pk);
    gemm_tf32<false><<<gg, 256>>>(value, Wv, bv, nullptr, pv);

    transpose_v<<<dim3(16, BHH), 256>>>(pv, pvT);

    const int smem_bytes = (128*QP + 128*QP + 64*SP + 128*SP + 128 + 128 + 512 + 512)
                           * (int)sizeof(float);   // 176128
    cudaFuncSetAttribute(attn_tc, cudaFuncAttributeMaxDynamicSharedMemorySize, smem_bytes);
    attn_tc<<<dim3(LL/128, BHH), 256, smem_bytes>>>(pq, pk, pvT, attn, pctx);

    gemm_tf32<true><<<gg, 256>>>(pctx, Wo, bo, query, px);
    ln_kernel<<<MROWS/8, 256>>>(px, wa, wb, out);
}